// round 8
// baseline (speedup 1.0000x reference)
#include <cuda_runtime.h>
#include <math.h>
#include <stdint.h>

#define BB 2
#define SS 2048
#define HIDD 1024
#define HH 16
#define DD 64
#define KKEEP 204
#define QT 16
#define CK 1024
#define CKP 1036  // 1036*4 % 16 == 0 (float4-aligned); 4*1036 % 32 == 16 (2-way worst store)
#define DC 16
#define PA 132    // 132*4 % 16 == 0

// ---------------- device scratch ----------------
__device__ float g_Q[BB*HH*SS*DD];    // [b,h,s,d]
__device__ float g_K[BB*HH*SS*DD];
__device__ float g_V[BB*HH*SS*DD];
__device__ float g_AO[BB*SS*HIDD];    // attention output, [b,s,hid]
__device__ float g_Vsum[BB*HH*DD];    // per-(b,h) column sum of V

// =====================================================================
// GEMM core: 128x128 tile, BK=16, double-buffered, 256 thr, 8x8/thread
// =====================================================================
struct GemmAcc { float a[8][8]; };

__device__ __forceinline__ void gemm_core(
    const float* __restrict__ A, const float* __restrict__ W,
    int bm, int bn, int t,
    float (*As)[16][PA], float (*Bs)[16][128], GemmAcc& R)
{
#pragma unroll
    for (int i = 0; i < 8; i++)
#pragma unroll
        for (int j = 0; j < 8; j++) R.a[i][j] = 0.f;

    const int ar0 = t >> 2, ac4 = (t & 3) * 4;
    const int bk0 = t >> 5, bc4 = (t & 31) * 4;

    float4 a0, a1, b0, b1;
    a0 = *(const float4*)&A[(size_t)(bm + ar0     ) * HIDD + ac4];
    a1 = *(const float4*)&A[(size_t)(bm + ar0 + 64) * HIDD + ac4];
    b0 = *(const float4*)&W[(size_t)(bk0    ) * HIDD + bn + bc4];
    b1 = *(const float4*)&W[(size_t)(bk0 + 8) * HIDD + bn + bc4];
    {
        As[0][ac4+0][ar0] = a0.x; As[0][ac4+1][ar0] = a0.y;
        As[0][ac4+2][ar0] = a0.z; As[0][ac4+3][ar0] = a0.w;
        As[0][ac4+0][ar0+64] = a1.x; As[0][ac4+1][ar0+64] = a1.y;
        As[0][ac4+2][ar0+64] = a1.z; As[0][ac4+3][ar0+64] = a1.w;
        *(float4*)&Bs[0][bk0  ][bc4] = b0;
        *(float4*)&Bs[0][bk0+8][bc4] = b1;
    }
    __syncthreads();

    int buf = 0;
    const int tx = t & 15, ty = t >> 4;
    for (int k0 = 16; ; k0 += 16) {
        const bool more = (k0 < HIDD);
        if (more) {
            a0 = *(const float4*)&A[(size_t)(bm + ar0     ) * HIDD + k0 + ac4];
            a1 = *(const float4*)&A[(size_t)(bm + ar0 + 64) * HIDD + k0 + ac4];
            b0 = *(const float4*)&W[(size_t)(k0 + bk0    ) * HIDD + bn + bc4];
            b1 = *(const float4*)&W[(size_t)(k0 + bk0 + 8) * HIDD + bn + bc4];
        }
#pragma unroll
        for (int kk = 0; kk < 16; kk++) {
            float a[8], b[8];
            *(float4*)&a[0] = *(float4*)&As[buf][kk][ty*4];
            *(float4*)&a[4] = *(float4*)&As[buf][kk][64 + ty*4];
            *(float4*)&b[0] = *(float4*)&Bs[buf][kk][tx*4];
            *(float4*)&b[4] = *(float4*)&Bs[buf][kk][64 + tx*4];
#pragma unroll
            for (int i = 0; i < 8; i++)
#pragma unroll
                for (int j = 0; j < 8; j++) R.a[i][j] += a[i] * b[j];
        }
        if (!more) break;
        const int nb = buf ^ 1;
        As[nb][ac4+0][ar0] = a0.x; As[nb][ac4+1][ar0] = a0.y;
        As[nb][ac4+2][ar0] = a0.z; As[nb][ac4+3][ar0] = a0.w;
        As[nb][ac4+0][ar0+64] = a1.x; As[nb][ac4+1][ar0+64] = a1.y;
        As[nb][ac4+2][ar0+64] = a1.z; As[nb][ac4+3][ar0+64] = a1.w;
        *(float4*)&Bs[nb][bk0  ][bc4] = b0;
        *(float4*)&Bs[nb][bk0+8][bc4] = b1;
        __syncthreads();
        buf = nb;
    }
}

__device__ __forceinline__ int row_of(int i, int tyx) {
    return (i < 4) ? (tyx*4 + i) : (64 + tyx*4 + i - 4);
}

__global__ __launch_bounds__(256, 2)
void gemm_qkv(const float* __restrict__ x,
              const float* __restrict__ Wq, const float* __restrict__ bq,
              const float* __restrict__ Wk, const float* __restrict__ bk,
              const float* __restrict__ Wv, const float* __restrict__ bv)
{
    __shared__ float As[2][16][PA];
    __shared__ float Bs[2][16][128];
    const int z = blockIdx.z;
    const float* W    = (z == 0) ? Wq : (z == 1) ? Wk : Wv;
    const float* bias = (z == 0) ? bq : (z == 1) ? bk : bv;
    float* C          = (z == 0) ? g_Q : (z == 1) ? g_K : g_V;

    const int bm = blockIdx.y * 128, bn = blockIdx.x * 128;
    const int t = threadIdx.x, tx = t & 15, ty = t >> 4;
    GemmAcc R;
    gemm_core(x, W, bm, bn, t, As, Bs, R);

#pragma unroll
    for (int i = 0; i < 8; i++) {
        const int m = bm + row_of(i, ty);
        const int b_ = m >> 11, s = m & 2047;
#pragma unroll
        for (int j = 0; j < 8; j++) {
            const int n = bn + row_of(j, tx);
            const int h = n >> 6, d = n & 63;
            C[(((size_t)(b_*HH + h))*SS + s)*DD + d] = R.a[i][j] + bias[n];
        }
    }
}

__global__ __launch_bounds__(256, 2)
void gemm_o(const float* __restrict__ Wo, const float* __restrict__ bo,
            float* __restrict__ out)
{
    __shared__ float As[2][16][PA];
    __shared__ float Bs[2][16][128];
    const int bm = blockIdx.y * 128, bn = blockIdx.x * 128;
    const int t = threadIdx.x, tx = t & 15, ty = t >> 4;
    GemmAcc R;
    gemm_core(g_AO, Wo, bm, bn, t, As, Bs, R);

#pragma unroll
    for (int i = 0; i < 8; i++) {
        const int m = bm + row_of(i, ty);
#pragma unroll
        for (int j = 0; j < 8; j++) {
            const int n = bn + row_of(j, tx);
            out[(size_t)m * HIDD + n] = R.a[i][j] + bo[n];
        }
    }
}

// ---------------- per-(b,h) V column sums ----------------
__global__ __launch_bounds__(512)
void vsum_kernel()
{
    __shared__ float red[8][64];
    const int bh = blockIdx.x;
    const int d = threadIdx.x & 63, sub = threadIdx.x >> 6;
    const float* vp = g_V + (size_t)bh*SS*DD + (size_t)sub*256*DD + d;
    float s0=0,s1=0,s2=0,s3=0;
#pragma unroll 4
    for (int i = 0; i < 256; i += 4) {
        s0 += vp[(size_t)(i+0)*DD];
        s1 += vp[(size_t)(i+1)*DD];
        s2 += vp[(size_t)(i+2)*DD];
        s3 += vp[(size_t)(i+3)*DD];
    }
    red[sub][d] = (s0+s1)+(s2+s3);
    __syncthreads();
    if (sub == 0) {
        float a = 0.f;
#pragma unroll
        for (int j = 0; j < 8; j++) a += red[j][d];
        g_Vsum[bh*DD + d] = a;
    }
}

// =====================================================================
// fused attention: scores + fused hist/max epilogue + exact top-204 + sparse softmax@V
// =====================================================================
__device__ __forceinline__ unsigned fkey(float f)
{
    unsigned u = __float_as_uint(f);
    return (u & 0x80000000u) ? ~u : (u | 0x80000000u);  // monotonic ascending
}
__device__ __forceinline__ float fkeyinv(unsigned k)
{
    unsigned u = (k & 0x80000000u) ? (k & 0x7fffffffu) : ~k;
    return __uint_as_float(u);
}

__global__ __launch_bounds__(512, 1)
void attn_kernel()
{
    extern __shared__ float smem[];
    float*    sc    = smem;                         // [QT][SS]      131072 B
    int*      hist  = (int*)(sc + QT*SS);           // [QT][256]      16384 B
    unsigned* rmaxk = (unsigned*)(hist + QT*256);   // [16] + pad       128 B
    float*    Kt    = (float*)(rmaxk + 32);         // [DC][CKP]      66304 B
    float*    Qs    = Kt + DC*CKP;                  // [QT][DD]        4096 B
    // phase B/C alias Kt:
    int* sel = (int*)Kt;                            // [QT][KKEEP]
    int* wsi = sel + QT*KKEEP;                      // [16][4]

    const int t    = threadIdx.x;
    const int tile = blockIdx.x;
    const int bh   = tile / (SS/QT);
    const int q0   = (tile % (SS/QT)) * QT;
    const float* Qg = g_Q + (size_t)bh*SS*DD;
    const float* Kg = g_K + (size_t)bh*SS*DD;
    const float* Vg = g_V + (size_t)bh*SS*DD;

    // zero hist + rmaxk (contiguous: 4096 + 32 ints)
    for (int i = t; i < QT*256 + 32; i += 512) hist[i] = 0;
    // load Q rows (16 x 64)
    if (t < 256) {
        int r = t >> 4, c = (t & 15) * 4;
        *(float4*)&Qs[r*DD + c] = *(const float4*)&Qg[(size_t)(q0 + r)*DD + c];
    }
    __syncthreads();

    // ---- phase A: scores, 4q x 8k register tile (keys k0..k0+3 and +512) ----
    const float scale = 0.125f;   // 1/sqrt(64)
    const int g  = t >> 7;        // row group: rows g, g+4, g+8, g+12
    const int k0 = (t & 127) * 4; // first key quad; second quad at +512

    unsigned tmax[4] = {0u,0u,0u,0u};

    for (int kc = 0; kc < SS; kc += CK) {
        float acc[4][8];
#pragma unroll
        for (int i = 0; i < 4; i++)
#pragma unroll
            for (int j = 0; j < 8; j++) acc[i][j] = 0.f;

        for (int dc = 0; dc < DD; dc += DC) {
            // load K chunk transposed: Kt[dlocal][key], 1024 keys x 16 d
#pragma unroll
            for (int it = 0; it < 8; it++) {
                int idx = it * 512 + t;    // 0..4095
                int key = idx >> 2;        // 0..1023
                int jj  = idx & 3;
                float4 v = *(const float4*)&Kg[(size_t)(kc + key)*DD + dc + jj*4];
                Kt[(jj*4+0)*CKP + key] = v.x;
                Kt[(jj*4+1)*CKP + key] = v.y;
                Kt[(jj*4+2)*CKP + key] = v.z;
                Kt[(jj*4+3)*CKP + key] = v.w;
            }
            __syncthreads();
#pragma unroll
            for (int d4 = 0; d4 < DC; d4 += 4) {
                float q[4][4], ka[4][4], kb[4][4];
#pragma unroll
                for (int i = 0; i < 4; i++)
                    *(float4*)q[i] = *(const float4*)&Qs[(g + 4*i)*DD + dc + d4];
#pragma unroll
                for (int dd = 0; dd < 4; dd++) {
                    *(float4*)ka[dd] = *(const float4*)&Kt[(d4+dd)*CKP + k0];
                    *(float4*)kb[dd] = *(const float4*)&Kt[(d4+dd)*CKP + k0 + 512];
                }
#pragma unroll
                for (int i = 0; i < 4; i++)
#pragma unroll
                    for (int dd = 0; dd < 4; dd++)
#pragma unroll
                        for (int j = 0; j < 4; j++) {
                            acc[i][j]   += q[i][dd] * ka[dd][j];
                            acc[i][j+4] += q[i][dd] * kb[dd][j];
                        }
            }
            __syncthreads();
        }
        // epilogue: scale, store scores, fused pass-0 histogram + running max
#pragma unroll
        for (int i = 0; i < 4; i++) {
            const int row = g + 4*i;
            float vv[8];
#pragma unroll
            for (int j = 0; j < 8; j++) vv[j] = acc[i][j] * scale;
            *(float4*)&sc[row*SS + kc + k0] =
                make_float4(vv[0], vv[1], vv[2], vv[3]);
            *(float4*)&sc[row*SS + kc + 512 + k0] =
                make_float4(vv[4], vv[5], vv[6], vv[7]);
#pragma unroll
            for (int j = 0; j < 8; j++) {
                unsigned key = fkey(vv[j]);
                if (key > tmax[i]) tmax[i] = key;
                unsigned bin = key >> 24;
                unsigned mk = __match_any_sync(0xffffffffu, bin);
                if ((t & 31) == (__ffs(mk) - 1))
                    atomicAdd(&hist[row*256 + (int)bin], __popc(mk));
            }
        }
    }
    // row max: warp-reduce then one atomicMax per row per warp
#pragma unroll
    for (int i = 0; i < 4; i++) {
        unsigned v = tmax[i];
#pragma unroll
        for (int off = 16; off; off >>= 1) {
            unsigned o = __shfl_xor_sync(0xffffffffu, v, off);
            v = (o > v) ? o : v;
        }
        if ((t & 31) == 0) atomicMax(&rmaxk[g + 4*i], v);
    }
    __syncthreads();

    // ---- phase B: per-warp exact top-204 radix select (pass 0 precomputed) ----
    const int w = t >> 5, lane = t & 31;
    const unsigned ltmask = (1u << lane) - 1u;
    const int qi = w;
    const float* row = sc + qi*SS;
    int* h = hist + w*256;

    const float m = fmaxf(fkeyinv(rmaxk[qi]), 0.0f);  // sparse row contains zeros

    int rem = KKEEP;
    unsigned prefix = 0;
#pragma unroll
    for (int pass = 0; pass < 4; pass++) {
        int shift = 24 - pass*8;
        if (pass > 0) {
            for (int i = lane; i < 256; i += 32) h[i] = 0;
            __syncwarp();
            for (int i = lane; i < SS; i += 32) {
                unsigned u = fkey(row[i]);
                if ((u >> (shift + 8)) == prefix)
                    atomicAdd(&h[(u >> shift) & 255], 1);
            }
        }
        __syncwarp();
        if (lane == 0) {
            int cum = 0, bsel = 0, r2 = rem;
            for (int bbin = 255; bbin >= 0; bbin--) {
                int c = h[bbin];
                if (cum + c >= rem) { bsel = bbin; r2 = rem - cum; break; }
                cum += c;
            }
            wsi[w*4+0] = bsel;
            wsi[w*4+1] = r2;
        }
        __syncwarp();
        prefix = (prefix << 8) | (unsigned)wsi[w*4+0];
        rem = wsi[w*4+1];
    }
    const unsigned T = prefix;   // key of the 204th largest
    const int need_eq = rem;     // #equal-to-T taken (lowest index first)

    // selection list (index-ordered tie-break, matches jax top_k) + Z
    int cnt = 0, eqtaken = 0;
    float zacc = 0.f;
    for (int i0 = 0; i0 < SS; i0 += 32) {
        int i = i0 + lane;
        float v = row[i];
        unsigned u = fkey(v);
        bool gt = u > T;
        bool eq = (u == T);
        unsigned em = __ballot_sync(~0u, eq);
        bool seleq = eq && (eqtaken + __popc(em & ltmask)) < need_eq;
        eqtaken += __popc(em);
        bool selected = gt || seleq;
        unsigned smk = __ballot_sync(~0u, selected);
        int pos = cnt + __popc(smk & ltmask);
        cnt += __popc(smk);
        if (selected && pos < KKEEP) {
            sel[qi*KKEEP + pos] = i;
            zacc += __expf(v - m);
        }
    }
#pragma unroll
    for (int off = 16; off; off >>= 1)
        zacc += __shfl_xor_sync(~0u, zacc, off);
    const float e0 = __expf(-m);
    const float Z = zacc + (float)(SS - KKEEP) * e0;
    const float invZ = 1.0f / Z;

    // ---- phase C: out = (sum_sel (e_i - e0) V_i + e0 * Vsum) / Z ----
    const int d0 = 2*lane;
    float2 a = *(const float2*)&g_Vsum[bh*DD + d0];
    a.x *= e0; a.y *= e0;
#pragma unroll 2
    for (int j = 0; j < KKEEP; j++) {
        int idx = sel[qi*KKEEP + j];
        float wgt = __expf(row[idx] - m) - e0;
        float2 vr = *(const float2*)&Vg[(size_t)idx * DD + d0];
        a.x += wgt * vr.x;
        a.y += wgt * vr.y;
    }
    const int b_ = bh / HH, hh = bh % HH;
    float* ao = g_AO + ((size_t)(b_*SS + q0 + qi))*HIDD + hh*DD;
    ao[d0]   = a.x * invZ;
    ao[d0+1] = a.y * invZ;
}

// ---------------- launcher ----------------
extern "C" void kernel_launch(void* const* d_in, const int* in_sizes, int n_in,
                              void* d_out, int out_size)
{
    (void)in_sizes; (void)n_in; (void)out_size;
    const float* x  = (const float*)d_in[0];
    const float* Wq = (const float*)d_in[1];
    const float* bq = (const float*)d_in[2];
    const float* Wk = (const float*)d_in[3];
    const float* bk = (const float*)d_in[4];
    const float* Wv = (const float*)d_in[5];
    const float* bv = (const float*)d_in[6];
    const float* Wo = (const float*)d_in[7];
    const float* bo = (const float*)d_in[8];
    float* out = (float*)d_out;

    const int smem_bytes =
        (QT*SS + DC*CKP + QT*DD) * 4 + (QT*256 + 32) * 4;  // 217984
    cudaFuncSetAttribute(attn_kernel, cudaFuncAttributeMaxDynamicSharedMemorySize,
                         smem_bytes);

    dim3 gqkv(HIDD/128, (BB*SS)/128, 3);   // 8 x 32 x 3
    gemm_qkv<<<gqkv, 256>>>(x, Wq, bq, Wk, bk, Wv, bv);

    vsum_kernel<<<BB*HH, 512>>>();

    attn_kernel<<<BB*HH*(SS/QT), 512, smem_bytes>>>();

    dim3 go(HIDD/128, (BB*SS)/128);        // 8 x 32
    gemm_o<<<go, 256>>>(Wo, bo, out);
}

// round 11
// speedup vs baseline: 1.3040x; 1.3040x over previous
#include <cuda_runtime.h>
#include <math.h>
#include <stdint.h>

#define BB 2
#define SS 2048
#define HIDD 1024
#define HH 16
#define DD 64
#define KKEEP 204
#define PA 132    // gemm As pad: 132*4 % 16 == 0
#define QP 68     // scores Qs row stride (floats): 272 B, 16B-aligned
#define KP 132    // scores Kt row stride (floats): 528 B, 16B-aligned

// ---------------- device scratch ----------------
__device__ float g_Q[BB*HH*SS*DD];     // [b,h,s,d]
__device__ float g_K[BB*HH*SS*DD];
__device__ float g_V[BB*HH*SS*DD];
__device__ float g_S[(size_t)BB*HH*SS*SS];  // scores [bh][q][k]  (536 MB)
__device__ float g_AO[BB*SS*HIDD];     // attention output, [b,s,hid]
__device__ float g_Vsum[BB*HH*DD];     // per-(b,h) column sum of V

// =====================================================================
// GEMM core: 128x128 tile, BK=16, double-buffered, 256 thr, 8x8/thread
// =====================================================================
struct GemmAcc { float a[8][8]; };

__device__ __forceinline__ void gemm_core(
    const float* __restrict__ A, const float* __restrict__ W,
    int bm, int bn, int t,
    float (*As)[16][PA], float (*Bs)[16][128], GemmAcc& R)
{
#pragma unroll
    for (int i = 0; i < 8; i++)
#pragma unroll
        for (int j = 0; j < 8; j++) R.a[i][j] = 0.f;

    const int ar0 = t >> 2, ac4 = (t & 3) * 4;
    const int bk0 = t >> 5, bc4 = (t & 31) * 4;

    float4 a0, a1, b0, b1;
    a0 = *(const float4*)&A[(size_t)(bm + ar0     ) * HIDD + ac4];
    a1 = *(const float4*)&A[(size_t)(bm + ar0 + 64) * HIDD + ac4];
    b0 = *(const float4*)&W[(size_t)(bk0    ) * HIDD + bn + bc4];
    b1 = *(const float4*)&W[(size_t)(bk0 + 8) * HIDD + bn + bc4];
    {
        As[0][ac4+0][ar0] = a0.x; As[0][ac4+1][ar0] = a0.y;
        As[0][ac4+2][ar0] = a0.z; As[0][ac4+3][ar0] = a0.w;
        As[0][ac4+0][ar0+64] = a1.x; As[0][ac4+1][ar0+64] = a1.y;
        As[0][ac4+2][ar0+64] = a1.z; As[0][ac4+3][ar0+64] = a1.w;
        *(float4*)&Bs[0][bk0  ][bc4] = b0;
        *(float4*)&Bs[0][bk0+8][bc4] = b1;
    }
    __syncthreads();

    int buf = 0;
    const int tx = t & 15, ty = t >> 4;
    for (int k0 = 16; ; k0 += 16) {
        const bool more = (k0 < HIDD);
        if (more) {
            a0 = *(const float4*)&A[(size_t)(bm + ar0     ) * HIDD + k0 + ac4];
            a1 = *(const float4*)&A[(size_t)(bm + ar0 + 64) * HIDD + k0 + ac4];
            b0 = *(const float4*)&W[(size_t)(k0 + bk0    ) * HIDD + bn + bc4];
            b1 = *(const float4*)&W[(size_t)(k0 + bk0 + 8) * HIDD + bn + bc4];
        }
#pragma unroll
        for (int kk = 0; kk < 16; kk++) {
            float a[8], b[8];
            *(float4*)&a[0] = *(float4*)&As[buf][kk][ty*4];
            *(float4*)&a[4] = *(float4*)&As[buf][kk][64 + ty*4];
            *(float4*)&b[0] = *(float4*)&Bs[buf][kk][tx*4];
            *(float4*)&b[4] = *(float4*)&Bs[buf][kk][64 + tx*4];
#pragma unroll
            for (int i = 0; i < 8; i++)
#pragma unroll
                for (int j = 0; j < 8; j++) R.a[i][j] += a[i] * b[j];
        }
        if (!more) break;
        const int nb = buf ^ 1;
        As[nb][ac4+0][ar0] = a0.x; As[nb][ac4+1][ar0] = a0.y;
        As[nb][ac4+2][ar0] = a0.z; As[nb][ac4+3][ar0] = a0.w;
        As[nb][ac4+0][ar0+64] = a1.x; As[nb][ac4+1][ar0+64] = a1.y;
        As[nb][ac4+2][ar0+64] = a1.z; As[nb][ac4+3][ar0+64] = a1.w;
        *(float4*)&Bs[nb][bk0  ][bc4] = b0;
        *(float4*)&Bs[nb][bk0+8][bc4] = b1;
        __syncthreads();
        buf = nb;
    }
}

__device__ __forceinline__ int row_of(int i, int tyx) {
    return (i < 4) ? (tyx*4 + i) : (64 + tyx*4 + i - 4);
}

__global__ __launch_bounds__(256, 2)
void gemm_qkv(const float* __restrict__ x,
              const float* __restrict__ Wq, const float* __restrict__ bq,
              const float* __restrict__ Wk, const float* __restrict__ bk,
              const float* __restrict__ Wv, const float* __restrict__ bv)
{
    __shared__ float As[2][16][PA];
    __shared__ float Bs[2][16][128];
    const int z = blockIdx.z;
    const float* W    = (z == 0) ? Wq : (z == 1) ? Wk : Wv;
    const float* bias = (z == 0) ? bq : (z == 1) ? bk : bv;
    float* C          = (z == 0) ? g_Q : (z == 1) ? g_K : g_V;

    const int bm = blockIdx.y * 128, bn = blockIdx.x * 128;
    const int t = threadIdx.x, tx = t & 15, ty = t >> 4;
    GemmAcc R;
    gemm_core(x, W, bm, bn, t, As, Bs, R);

#pragma unroll
    for (int i = 0; i < 8; i++) {
        const int m = bm + row_of(i, ty);
        const int b_ = m >> 11, s = m & 2047;
#pragma unroll
        for (int j = 0; j < 8; j++) {
            const int n = bn + row_of(j, tx);
            const int h = n >> 6, d = n & 63;
            C[(((size_t)(b_*HH + h))*SS + s)*DD + d] = R.a[i][j] + bias[n];
        }
    }
}

__global__ __launch_bounds__(256, 2)
void gemm_o(const float* __restrict__ Wo, const float* __restrict__ bo,
            float* __restrict__ out)
{
    __shared__ float As[2][16][PA];
    __shared__ float Bs[2][16][128];
    const int bm = blockIdx.y * 128, bn = blockIdx.x * 128;
    const int t = threadIdx.x, tx = t & 15, ty = t >> 4;
    GemmAcc R;
    gemm_core(g_AO, Wo, bm, bn, t, As, Bs, R);

#pragma unroll
    for (int i = 0; i < 8; i++) {
        const int m = bm + row_of(i, ty);
#pragma unroll
        for (int j = 0; j < 8; j++) {
            const int n = bn + row_of(j, tx);
            out[(size_t)m * HIDD + n] = R.a[i][j] + bo[n];
        }
    }
}

// ---------------- per-(b,h) V column sums ----------------
__global__ __launch_bounds__(512)
void vsum_kernel()
{
    __shared__ float red[8][64];
    const int bh = blockIdx.x;
    const int d = threadIdx.x & 63, sub = threadIdx.x >> 6;
    const float* vp = g_V + (size_t)bh*SS*DD + (size_t)sub*256*DD + d;
    float s0=0,s1=0,s2=0,s3=0;
#pragma unroll 4
    for (int i = 0; i < 256; i += 4) {
        s0 += vp[(size_t)(i+0)*DD];
        s1 += vp[(size_t)(i+1)*DD];
        s2 += vp[(size_t)(i+2)*DD];
        s3 += vp[(size_t)(i+3)*DD];
    }
    red[sub][d] = (s0+s1)+(s2+s3);
    __syncthreads();
    if (sub == 0) {
        float a = 0.f;
#pragma unroll
        for (int j = 0; j < 8; j++) a += red[j][d];
        g_Vsum[bh*DD + d] = a;
    }
}

// =====================================================================
// scores kernel: S[bh][q][k] = (Q . K) / 8, 128x128 tiles, K=64
// grid (16, 16, 32), 256 threads, 8q x 8k per thread
// =====================================================================
__global__ __launch_bounds__(256, 2)
void scores_kernel()
{
    extern __shared__ float sm[];
    float* Qs = sm;               // [128][QP]
    float* Kt = sm + 128*QP;      // [64][KP]  (d-major, transposed)

    const int bh = blockIdx.z;
    const int bm = blockIdx.y * 128;  // q rows
    const int bn = blockIdx.x * 128;  // keys
    const int t  = threadIdx.x;
    const int tx = t & 15, ty = t >> 4;
    const float* Qg = g_Q + (size_t)bh*SS*DD;
    const float* Kg = g_K + (size_t)bh*SS*DD;

    // load Q tile 128x64 (row-major, stride QP)
#pragma unroll
    for (int it = 0; it < 8; it++) {
        int idx = it*256 + t;           // 0..2047
        int r = idx >> 4, c4 = (idx & 15)*4;
        *(float4*)&Qs[r*QP + c4] = *(const float4*)&Qg[(size_t)(bm + r)*DD + c4];
    }
    // load K tile 128x64 transposed -> Kt[d][key]
#pragma unroll
    for (int it = 0; it < 8; it++) {
        int idx = it*256 + t;
        int key = idx >> 4, c4 = idx & 15;
        float4 v = *(const float4*)&Kg[(size_t)(bn + key)*DD + c4*4];
        Kt[(c4*4+0)*KP + key] = v.x;
        Kt[(c4*4+1)*KP + key] = v.y;
        Kt[(c4*4+2)*KP + key] = v.z;
        Kt[(c4*4+3)*KP + key] = v.w;
    }
    __syncthreads();

    float acc[8][8];
#pragma unroll
    for (int i = 0; i < 8; i++)
#pragma unroll
        for (int j = 0; j < 8; j++) acc[i][j] = 0.f;

    // keys per thread: tx*4+{0..3} and 64+tx*4+{0..3}
#pragma unroll
    for (int d4 = 0; d4 < DD; d4 += 4) {
        float4 qv[8];
#pragma unroll
        for (int i = 0; i < 8; i++)
            qv[i] = *(const float4*)&Qs[(ty*8 + i)*QP + d4];
#pragma unroll
        for (int dd = 0; dd < 4; dd++) {
            float4 ka = *(const float4*)&Kt[(d4+dd)*KP + tx*4];
            float4 kb = *(const float4*)&Kt[(d4+dd)*KP + 64 + tx*4];
#pragma unroll
            for (int i = 0; i < 8; i++) {
                float qd = (dd==0)?qv[i].x:(dd==1)?qv[i].y:(dd==2)?qv[i].z:qv[i].w;
                acc[i][0] += qd*ka.x; acc[i][1] += qd*ka.y;
                acc[i][2] += qd*ka.z; acc[i][3] += qd*ka.w;
                acc[i][4] += qd*kb.x; acc[i][5] += qd*kb.y;
                acc[i][6] += qd*kb.z; acc[i][7] += qd*kb.w;
            }
        }
    }

    const float scale = 0.125f;
    float* Sg = g_S + (size_t)bh*SS*SS;
#pragma unroll
    for (int i = 0; i < 8; i++) {
        const size_t roff = (size_t)(bm + ty*8 + i)*SS + bn;
        *(float4*)&Sg[roff + tx*4] =
            make_float4(acc[i][0]*scale, acc[i][1]*scale, acc[i][2]*scale, acc[i][3]*scale);
        *(float4*)&Sg[roff + 64 + tx*4] =
            make_float4(acc[i][4]*scale, acc[i][5]*scale, acc[i][6]*scale, acc[i][7]*scale);
    }
}

// =====================================================================
// select kernel: one block per query row. exact top-204 + sparse softmax@V
// grid 65536, 256 threads, ~12 KB smem -> 8 blocks/SM
// =====================================================================
__device__ __forceinline__ unsigned fkey(float f)
{
    unsigned u = __float_as_uint(f);
    return (u & 0x80000000u) ? ~u : (u | 0x80000000u);
}
__device__ __forceinline__ float fkeyinv(unsigned k)
{
    unsigned u = (k & 0x80000000u) ? (k & 0x7fffffffu) : ~k;
    return __uint_as_float(u);
}

__global__ __launch_bounds__(256)
void select_kernel()
{
    __shared__ float row[SS];
    __shared__ int   hist[256];
    __shared__ int   wgt_cnt[8], weq_cnt[8], weq_b[8], wbase[8];
    __shared__ unsigned wmax[8];
    __shared__ int   sel[KKEEP];
    __shared__ float wgt[KKEEP];
    __shared__ float partial[4][64];
    __shared__ float zred[8];
    __shared__ int   sbin, srem;
    __shared__ float s_invZ;

    const int t = threadIdx.x, w = t >> 5, lane = t & 31;
    const unsigned ltmask = (1u << lane) - 1u;
    const int rowid = blockIdx.x;            // = bh*2048 + q
    const int bh = rowid >> 11, q = rowid & 2047;
    const float* Sg = g_S + (size_t)rowid * SS;
    const float* Vg = g_V + (size_t)bh*SS*DD;

    // load row + zero hist
    {
        const float4* s4 = (const float4*)Sg;
#pragma unroll
        for (int it = 0; it < 2; it++)
            ((float4*)row)[it*256 + t] = s4[it*256 + t];
    }
    hist[t] = 0;
    __syncthreads();

    // pass 0 histogram (match-aggregated) + row max
    unsigned mymax = 0;
#pragma unroll
    for (int step = 0; step < 8; step++) {
        float v = row[step*256 + t];
        unsigned u = fkey(v);
        if (u > mymax) mymax = u;
        unsigned bin = u >> 24;
        unsigned mk = __match_any_sync(0xffffffffu, bin);
        if (lane == (__ffs(mk) - 1))
            atomicAdd(&hist[bin], __popc(mk));
    }
#pragma unroll
    for (int off = 16; off; off >>= 1) {
        unsigned o = __shfl_xor_sync(0xffffffffu, mymax, off);
        if (o > mymax) mymax = o;
    }
    if (lane == 0) wmax[w] = mymax;
    __syncthreads();
    unsigned gmax = wmax[0];
#pragma unroll
    for (int j = 1; j < 8; j++) if (wmax[j] > gmax) gmax = wmax[j];
    const float m  = fmaxf(fkeyinv(gmax), 0.0f);   // sparse row contains zeros
    const float e0 = __expf(-m);

    // radix select: find threshold key T and need_eq
    int rem = KKEEP;
    unsigned prefix = 0;
#pragma unroll
    for (int pass = 0; pass < 4; pass++) {
        const int shift = 24 - pass*8;
        if (pass > 0) {
            hist[t] = 0;
            __syncthreads();
#pragma unroll
            for (int step = 0; step < 8; step++) {
                unsigned u = fkey(row[step*256 + t]);
                if ((u >> (shift + 8)) == prefix)
                    atomicAdd(&hist[(u >> shift) & 255], 1);
            }
        }
        __syncthreads();
        if (t == 0) {
            int cum = 0, bsel = 0, r2 = rem;
            for (int b = 255; b >= 0; b--) {
                int c = hist[b];
                if (cum + c >= rem) { bsel = b; r2 = rem - cum; break; }
                cum += c;
            }
            sbin = bsel; srem = r2;
        }
        __syncthreads();
        prefix = (prefix << 8) | (unsigned)sbin;
        rem = srem;
        __syncthreads();
    }
    const unsigned T = prefix;
    const int need_eq = rem;

    // count gt/eq per warp over its contiguous 256-elem segment
    int cgt = 0, ceq = 0;
#pragma unroll
    for (int step = 0; step < 8; step++) {
        unsigned u = fkey(row[w*256 + step*32 + lane]);
        cgt += __popc(__ballot_sync(0xffffffffu, u > T));
        ceq += __popc(__ballot_sync(0xffffffffu, u == T));
    }
    if (lane == 0) { wgt_cnt[w] = cgt; weq_cnt[w] = ceq; }
    __syncthreads();
    if (t == 0) {
        int run = 0, eqr = 0;
        for (int ww = 0; ww < 8; ww++) {
            weq_b[ww] = eqr;
            int take = need_eq - eqr;
            if (take < 0) take = 0;
            if (take > weq_cnt[ww]) take = weq_cnt[ww];
            wbase[ww] = run;
            run += wgt_cnt[ww] + take;
            eqr += weq_cnt[ww];
        }
    }
    __syncthreads();

    // write selection list (globally index-ordered, ties by lowest index)
    {
        int pos = wbase[w], eqt = weq_b[w];
#pragma unroll
        for (int step = 0; step < 8; step++) {
            int i = w*256 + step*32 + lane;
            unsigned u = fkey(row[i]);
            bool gt = u > T, eq = (u == T);
            unsigned em = __ballot_sync(0xffffffffu, eq);
            bool seleq = eq && (eqt + __popc(em & ltmask)) < need_eq;
            eqt += __popc(em);
            unsigned smk = __ballot_sync(0xffffffffu, gt || seleq);
            int p = pos + __popc(smk & ltmask);
            pos += __popc(smk);
            if ((gt || seleq) && p < KKEEP) sel[p] = i;
        }
    }
    __syncthreads();

    // weights + Z
    float ez = 0.f;
    if (t < KKEEP) {
        float e = __expf(row[sel[t]] - m);
        wgt[t] = e - e0;
        ez = e;
    }
#pragma unroll
    for (int off = 16; off; off >>= 1)
        ez += __shfl_xor_sync(0xffffffffu, ez, off);
    if (lane == 0) zred[w] = ez;
    __syncthreads();
    if (t == 0) {
        float Z = (float)(SS - KKEEP) * e0;
#pragma unroll
        for (int j = 0; j < 8; j++) Z += zred[j];
        s_invZ = 1.0f / Z;
    }
    __syncthreads();

    // sparse attn @ V: 4-way split over selected rows, 64 d-lanes
    {
        const int c = t >> 6, d = t & 63;
        float acc = 0.f;
        for (int j = c; j < KKEEP; j += 4)
            acc += wgt[j] * Vg[(size_t)sel[j]*DD + d];
        partial[c][d] = acc;
    }
    __syncthreads();
    if (t < 64) {
        float s = partial[0][t] + partial[1][t] + partial[2][t] + partial[3][t]
                + e0 * g_Vsum[bh*DD + t];
        const int b_ = bh >> 4, hh = bh & 15;
        g_AO[((size_t)(b_*SS + q))*HIDD + hh*DD + t] = s * s_invZ;
    }
}

// ---------------- launcher ----------------
extern "C" void kernel_launch(void* const* d_in, const int* in_sizes, int n_in,
                              void* d_out, int out_size)
{
    (void)in_sizes; (void)n_in; (void)out_size;
    const float* x  = (const float*)d_in[0];
    const float* Wq = (const float*)d_in[1];
    const float* bq = (const float*)d_in[2];
    const float* Wk = (const float*)d_in[3];
    const float* bk = (const float*)d_in[4];
    const float* Wv = (const float*)d_in[5];
    const float* bv = (const float*)d_in[6];
    const float* Wo = (const float*)d_in[7];
    const float* bo = (const float*)d_in[8];
    float* out = (float*)d_out;

    const int sc_smem = (128*QP + 64*KP) * 4;   // 68608 B
    cudaFuncSetAttribute(scores_kernel, cudaFuncAttributeMaxDynamicSharedMemorySize,
                         sc_smem);

    dim3 gqkv(HIDD/128, (BB*SS)/128, 3);   // 8 x 32 x 3
    gemm_qkv<<<gqkv, 256>>>(x, Wq, bq, Wk, bk, Wv, bv);

    vsum_kernel<<<BB*HH, 512>>>();

    dim3 gsc(SS/128, SS/128, BB*HH);       // 16 x 16 x 32
    scores_kernel<<<gsc, 256, sc_smem>>>();

    select_kernel<<<BB*HH*SS, 256>>>();

    dim3 go(HIDD/128, (BB*SS)/128);        // 8 x 32
    gemm_o<<<go, 256>>>(Wo, bo, out);
}

// round 12
// speedup vs baseline: 1.3517x; 1.0367x over previous
#include <cuda_runtime.h>
#include <math.h>
#include <stdint.h>

#define BB 2
#define SS 2048
#define HIDD 1024
#define HH 16
#define DD 64
#define KKEEP 204
#define PA 132    // gemm As pad: 132*4 % 16 == 0
#define QP 68     // scores Qs row stride (floats): 272 B, 16B-aligned
#define KP 132    // scores Kt row stride (floats): 528 B, 16B-aligned

// ---------------- packed f32x2 helpers (sm_103a FFMA2 path) ----------------
__device__ __forceinline__ unsigned long long bcast2(float x)
{
    unsigned long long r;
    asm("mov.b64 %0, {%1, %1};" : "=l"(r) : "r"(__float_as_uint(x)));
    return r;
}
__device__ __forceinline__ void unpack2(unsigned long long v, float& x, float& y)
{
    unsigned lo, hi;
    asm("mov.b64 {%0, %1}, %2;" : "=r"(lo), "=r"(hi) : "l"(v));
    x = __uint_as_float(lo); y = __uint_as_float(hi);
}
__device__ __forceinline__ unsigned long long fma2(
    unsigned long long a, unsigned long long b, unsigned long long c)
{
    unsigned long long d;
    asm("fma.rn.f32x2 %0, %1, %2, %3;" : "=l"(d) : "l"(a), "l"(b), "l"(c));
    return d;
}

// ---------------- device scratch ----------------
__device__ float g_Q[BB*HH*SS*DD];     // [b,h,s,d]
__device__ float g_K[BB*HH*SS*DD];
__device__ float g_V[BB*HH*SS*DD];
__device__ float g_S[(size_t)BB*HH*SS*SS];  // scores [bh][q][k]  (536 MB)
__device__ float g_AO[BB*SS*HIDD];     // attention output, [b,s,hid]
__device__ float g_Vsum[BB*HH*DD];     // per-(b,h) column sum of V

// =====================================================================
// GEMM core: 128x128 tile, BK=16, double-buffered, 256 thr, 8x8/thread
// accumulators packed f32x2 along n (FFMA2)
// =====================================================================
struct GemmAcc { float a[8][8]; };

__device__ __forceinline__ void gemm_core(
    const float* __restrict__ A, const float* __restrict__ W,
    int bm, int bn, int t,
    float (*As)[16][PA], float (*Bs)[16][128], GemmAcc& R)
{
    unsigned long long acc2[8][4];
#pragma unroll
    for (int i = 0; i < 8; i++)
#pragma unroll
        for (int j = 0; j < 4; j++) acc2[i][j] = 0ULL;

    const int ar0 = t >> 2, ac4 = (t & 3) * 4;
    const int bk0 = t >> 5, bc4 = (t & 31) * 4;

    float4 a0, a1, b0, b1;
    a0 = *(const float4*)&A[(size_t)(bm + ar0     ) * HIDD + ac4];
    a1 = *(const float4*)&A[(size_t)(bm + ar0 + 64) * HIDD + ac4];
    b0 = *(const float4*)&W[(size_t)(bk0    ) * HIDD + bn + bc4];
    b1 = *(const float4*)&W[(size_t)(bk0 + 8) * HIDD + bn + bc4];
    {
        As[0][ac4+0][ar0] = a0.x; As[0][ac4+1][ar0] = a0.y;
        As[0][ac4+2][ar0] = a0.z; As[0][ac4+3][ar0] = a0.w;
        As[0][ac4+0][ar0+64] = a1.x; As[0][ac4+1][ar0+64] = a1.y;
        As[0][ac4+2][ar0+64] = a1.z; As[0][ac4+3][ar0+64] = a1.w;
        *(float4*)&Bs[0][bk0  ][bc4] = b0;
        *(float4*)&Bs[0][bk0+8][bc4] = b1;
    }
    __syncthreads();

    int buf = 0;
    const int tx = t & 15, ty = t >> 4;
    for (int k0 = 16; ; k0 += 16) {
        const bool more = (k0 < HIDD);
        if (more) {
            a0 = *(const float4*)&A[(size_t)(bm + ar0     ) * HIDD + k0 + ac4];
            a1 = *(const float4*)&A[(size_t)(bm + ar0 + 64) * HIDD + k0 + ac4];
            b0 = *(const float4*)&W[(size_t)(k0 + bk0    ) * HIDD + bn + bc4];
            b1 = *(const float4*)&W[(size_t)(k0 + bk0 + 8) * HIDD + bn + bc4];
        }
#pragma unroll
        for (int kk = 0; kk < 16; kk++) {
            float a[8];
            *(float4*)&a[0] = *(float4*)&As[buf][kk][ty*4];
            *(float4*)&a[4] = *(float4*)&As[buf][kk][64 + ty*4];
            ulonglong2 bA = *(const ulonglong2*)&Bs[buf][kk][tx*4];
            ulonglong2 bB = *(const ulonglong2*)&Bs[buf][kk][64 + tx*4];
#pragma unroll
            for (int i = 0; i < 8; i++) {
                unsigned long long pa = bcast2(a[i]);
                acc2[i][0] = fma2(pa, bA.x, acc2[i][0]);
                acc2[i][1] = fma2(pa, bA.y, acc2[i][1]);
                acc2[i][2] = fma2(pa, bB.x, acc2[i][2]);
                acc2[i][3] = fma2(pa, bB.y, acc2[i][3]);
            }
        }
        if (!more) break;
        const int nb = buf ^ 1;
        As[nb][ac4+0][ar0] = a0.x; As[nb][ac4+1][ar0] = a0.y;
        As[nb][ac4+2][ar0] = a0.z; As[nb][ac4+3][ar0] = a0.w;
        As[nb][ac4+0][ar0+64] = a1.x; As[nb][ac4+1][ar0+64] = a1.y;
        As[nb][ac4+2][ar0+64] = a1.z; As[nb][ac4+3][ar0+64] = a1.w;
        *(float4*)&Bs[nb][bk0  ][bc4] = b0;
        *(float4*)&Bs[nb][bk0+8][bc4] = b1;
        __syncthreads();
        buf = nb;
    }

    // unpack: acc2[i][jp] -> columns (2*jp, 2*jp+1) in the 8-wide j space
#pragma unroll
    for (int i = 0; i < 8; i++)
#pragma unroll
        for (int jp = 0; jp < 4; jp++)
            unpack2(acc2[i][jp], R.a[i][2*jp], R.a[i][2*jp+1]);
}

__device__ __forceinline__ int row_of(int i, int tyx) {
    return (i < 4) ? (tyx*4 + i) : (64 + tyx*4 + i - 4);
}

__global__ __launch_bounds__(256, 2)
void gemm_qkv(const float* __restrict__ x,
              const float* __restrict__ Wq, const float* __restrict__ bq,
              const float* __restrict__ Wk, const float* __restrict__ bk,
              const float* __restrict__ Wv, const float* __restrict__ bv)
{
    __shared__ __align__(16) float As[2][16][PA];
    __shared__ __align__(16) float Bs[2][16][128];
    const int z = blockIdx.z;
    const float* W    = (z == 0) ? Wq : (z == 1) ? Wk : Wv;
    const float* bias = (z == 0) ? bq : (z == 1) ? bk : bv;
    float* C          = (z == 0) ? g_Q : (z == 1) ? g_K : g_V;

    const int bm = blockIdx.y * 128, bn = blockIdx.x * 128;
    const int t = threadIdx.x, tx = t & 15, ty = t >> 4;
    GemmAcc R;
    gemm_core(x, W, bm, bn, t, As, Bs, R);

#pragma unroll
    for (int i = 0; i < 8; i++) {
        const int m = bm + row_of(i, ty);
        const int b_ = m >> 11, s = m & 2047;
#pragma unroll
        for (int j = 0; j < 8; j++) {
            const int n = bn + row_of(j, tx);
            const int h = n >> 6, d = n & 63;
            C[(((size_t)(b_*HH + h))*SS + s)*DD + d] = R.a[i][j] + bias[n];
        }
    }
}

__global__ __launch_bounds__(256, 2)
void gemm_o(const float* __restrict__ Wo, const float* __restrict__ bo,
            float* __restrict__ out)
{
    __shared__ __align__(16) float As[2][16][PA];
    __shared__ __align__(16) float Bs[2][16][128];
    const int bm = blockIdx.y * 128, bn = blockIdx.x * 128;
    const int t = threadIdx.x, tx = t & 15, ty = t >> 4;
    GemmAcc R;
    gemm_core(g_AO, Wo, bm, bn, t, As, Bs, R);

#pragma unroll
    for (int i = 0; i < 8; i++) {
        const int m = bm + row_of(i, ty);
#pragma unroll
        for (int j = 0; j < 8; j++) {
            const int n = bn + row_of(j, tx);
            out[(size_t)m * HIDD + n] = R.a[i][j] + bo[n];
        }
    }
}

// ---------------- per-(b,h) V column sums ----------------
__global__ __launch_bounds__(512)
void vsum_kernel()
{
    __shared__ float red[8][64];
    const int bh = blockIdx.x;
    const int d = threadIdx.x & 63, sub = threadIdx.x >> 6;
    const float* vp = g_V + (size_t)bh*SS*DD + (size_t)sub*256*DD + d;
    float s0=0,s1=0,s2=0,s3=0;
#pragma unroll 4
    for (int i = 0; i < 256; i += 4) {
        s0 += vp[(size_t)(i+0)*DD];
        s1 += vp[(size_t)(i+1)*DD];
        s2 += vp[(size_t)(i+2)*DD];
        s3 += vp[(size_t)(i+3)*DD];
    }
    red[sub][d] = (s0+s1)+(s2+s3);
    __syncthreads();
    if (sub == 0) {
        float a = 0.f;
#pragma unroll
        for (int j = 0; j < 8; j++) a += red[j][d];
        g_Vsum[bh*DD + d] = a;
    }
}

// =====================================================================
// scores kernel: S[bh][q][k] = (Q . K) / 8, 128x128 tiles, K=64
// grid (16, 16, 32), 256 threads, 8q x 8k per thread, FFMA2 packed
// =====================================================================
__global__ __launch_bounds__(256, 2)
void scores_kernel()
{
    extern __shared__ __align__(16) float sm[];
    float* Qs = sm;               // [128][QP]
    float* Kt = sm + 128*QP;      // [64][KP]  (d-major, transposed)

    const int bh = blockIdx.z;
    const int bm = blockIdx.y * 128;  // q rows
    const int bn = blockIdx.x * 128;  // keys
    const int t  = threadIdx.x;
    const int tx = t & 15, ty = t >> 4;
    const float* Qg = g_Q + (size_t)bh*SS*DD;
    const float* Kg = g_K + (size_t)bh*SS*DD;

    // load Q tile 128x64 (row-major, stride QP)
#pragma unroll
    for (int it = 0; it < 8; it++) {
        int idx = it*256 + t;           // 0..2047
        int r = idx >> 4, c4 = (idx & 15)*4;
        *(float4*)&Qs[r*QP + c4] = *(const float4*)&Qg[(size_t)(bm + r)*DD + c4];
    }
    // load K tile 128x64 transposed -> Kt[d][key]
#pragma unroll
    for (int it = 0; it < 8; it++) {
        int idx = it*256 + t;
        int key = idx >> 4, c4 = idx & 15;
        float4 v = *(const float4*)&Kg[(size_t)(bn + key)*DD + c4*4];
        Kt[(c4*4+0)*KP + key] = v.x;
        Kt[(c4*4+1)*KP + key] = v.y;
        Kt[(c4*4+2)*KP + key] = v.z;
        Kt[(c4*4+3)*KP + key] = v.w;
    }
    __syncthreads();

    unsigned long long acc2[8][4];
#pragma unroll
    for (int i = 0; i < 8; i++)
#pragma unroll
        for (int j = 0; j < 4; j++) acc2[i][j] = 0ULL;

    // keys per thread: tx*4+{0..3} and 64+tx*4+{0..3}, packed in pairs
#pragma unroll
    for (int d4 = 0; d4 < DD; d4 += 4) {
        float4 qv[8];
#pragma unroll
        for (int i = 0; i < 8; i++)
            qv[i] = *(const float4*)&Qs[(ty*8 + i)*QP + d4];
#pragma unroll
        for (int dd = 0; dd < 4; dd++) {
            ulonglong2 ka = *(const ulonglong2*)&Kt[(d4+dd)*KP + tx*4];
            ulonglong2 kb = *(const ulonglong2*)&Kt[(d4+dd)*KP + 64 + tx*4];
#pragma unroll
            for (int i = 0; i < 8; i++) {
                float qd = (dd==0)?qv[i].x:(dd==1)?qv[i].y:(dd==2)?qv[i].z:qv[i].w;
                unsigned long long pq = bcast2(qd);
                acc2[i][0] = fma2(pq, ka.x, acc2[i][0]);
                acc2[i][1] = fma2(pq, ka.y, acc2[i][1]);
                acc2[i][2] = fma2(pq, kb.x, acc2[i][2]);
                acc2[i][3] = fma2(pq, kb.y, acc2[i][3]);
            }
        }
    }

    const float scale = 0.125f;
    float* Sg = g_S + (size_t)bh*SS*SS;
#pragma unroll
    for (int i = 0; i < 8; i++) {
        float v[8];
#pragma unroll
        for (int jp = 0; jp < 4; jp++) unpack2(acc2[i][jp], v[2*jp], v[2*jp+1]);
        const size_t roff = (size_t)(bm + ty*8 + i)*SS + bn;
        *(float4*)&Sg[roff + tx*4] =
            make_float4(v[0]*scale, v[1]*scale, v[2]*scale, v[3]*scale);
        *(float4*)&Sg[roff + 64 + tx*4] =
            make_float4(v[4]*scale, v[5]*scale, v[6]*scale, v[7]*scale);
    }
}

// =====================================================================
// select kernel: one block per query row. exact top-204 + sparse softmax@V
// =====================================================================
__device__ __forceinline__ unsigned fkey(float f)
{
    unsigned u = __float_as_uint(f);
    return (u & 0x80000000u) ? ~u : (u | 0x80000000u);
}
__device__ __forceinline__ float fkeyinv(unsigned k)
{
    unsigned u = (k & 0x80000000u) ? (k & 0x7fffffffu) : ~k;
    return __uint_as_float(u);
}

__global__ __launch_bounds__(256)
void select_kernel()
{
    __shared__ __align__(16) float row[SS];
    __shared__ int   hist[256];
    __shared__ int   wgt_cnt[8], weq_cnt[8], weq_b[8], wbase[8];
    __shared__ unsigned wmax[8];
    __shared__ unsigned gmask[8][8], emask[8][8];   // cached ballots
    __shared__ int   sel[KKEEP];
    __shared__ float wgt[KKEEP];
    __shared__ float partial[4][64];
    __shared__ float zred[8];
    __shared__ int   sbin, srem;
    __shared__ float s_invZ;

    const int t = threadIdx.x, w = t >> 5, lane = t & 31;
    const unsigned ltmask = (1u << lane) - 1u;
    const int rowid = blockIdx.x;            // = bh*2048 + q
    const int bh = rowid >> 11, q = rowid & 2047;
    const float* Sg = g_S + (size_t)rowid * SS;
    const float* Vg = g_V + (size_t)bh*SS*DD;

    // load row + zero hist
    {
        const float4* s4 = (const float4*)Sg;
#pragma unroll
        for (int it = 0; it < 2; it++)
            ((float4*)row)[it*256 + t] = s4[it*256 + t];
    }
    hist[t] = 0;
    __syncthreads();

    // pass 0 histogram (match-aggregated) + row max
    unsigned mymax = 0;
#pragma unroll
    for (int step = 0; step < 8; step++) {
        float v = row[step*256 + t];
        unsigned u = fkey(v);
        if (u > mymax) mymax = u;
        unsigned bin = u >> 24;
        unsigned mk = __match_any_sync(0xffffffffu, bin);
        if (lane == (__ffs(mk) - 1))
            atomicAdd(&hist[bin], __popc(mk));
    }
#pragma unroll
    for (int off = 16; off; off >>= 1) {
        unsigned o = __shfl_xor_sync(0xffffffffu, mymax, off);
        if (o > mymax) mymax = o;
    }
    if (lane == 0) wmax[w] = mymax;
    __syncthreads();
    unsigned gmax = wmax[0];
#pragma unroll
    for (int j = 1; j < 8; j++) if (wmax[j] > gmax) gmax = wmax[j];
    const float m  = fmaxf(fkeyinv(gmax), 0.0f);   // sparse row contains zeros
    const float e0 = __expf(-m);

    // radix select: find threshold key T and need_eq
    int rem = KKEEP;
    unsigned prefix = 0;
#pragma unroll
    for (int pass = 0; pass < 4; pass++) {
        const int shift = 24 - pass*8;
        if (pass > 0) {
            hist[t] = 0;
            __syncthreads();
#pragma unroll
            for (int step = 0; step < 8; step++) {
                unsigned u = fkey(row[step*256 + t]);
                if ((u >> (shift + 8)) == prefix)
                    atomicAdd(&hist[(u >> shift) & 255], 1);
            }
        }
        __syncthreads();
        if (t == 0) {
            int cum = 0, bsel = 0, r2 = rem;
            for (int b = 255; b >= 0; b--) {
                int c = hist[b];
                if (cum + c >= rem) { bsel = b; r2 = rem - cum; break; }
                cum += c;
            }
            sbin = bsel; srem = r2;
        }
        __syncthreads();
        prefix = (prefix << 8) | (unsigned)sbin;
        rem = srem;
        __syncthreads();
    }
    const unsigned T = prefix;
    const int need_eq = rem;

    // count gt/eq per warp over its contiguous 256-elem segment; cache masks
    int cgt = 0, ceq = 0;
#pragma unroll
    for (int step = 0; step < 8; step++) {
        unsigned u = fkey(row[w*256 + step*32 + lane]);
        unsigned gm = __ballot_sync(0xffffffffu, u > T);
        unsigned em = __ballot_sync(0xffffffffu, u == T);
        cgt += __popc(gm);
        ceq += __popc(em);
        if (lane == 0) { gmask[w][step] = gm; emask[w][step] = em; }
    }
    if (lane == 0) { wgt_cnt[w] = cgt; weq_cnt[w] = ceq; }
    __syncthreads();
    if (t == 0) {
        int run = 0, eqr = 0;
        for (int ww = 0; ww < 8; ww++) {
            weq_b[ww] = eqr;
            int take = need_eq - eqr;
            if (take < 0) take = 0;
            if (take > weq_cnt[ww]) take = weq_cnt[ww];
            wbase[ww] = run;
            run += wgt_cnt[ww] + take;
            eqr += weq_cnt[ww];
        }
    }
    __syncthreads();

    // write selection list from cached masks (no fkey, no ballots)
    {
        int pos = wbase[w], eqt = weq_b[w];
#pragma unroll
        for (int step = 0; step < 8; step++) {
            const unsigned gm = gmask[w][step];
            const unsigned em = emask[w][step];
            int take = need_eq - eqt;
            if (take < 0) take = 0;
            const bool gt = (gm >> lane) & 1u;
            const bool eq = (em >> lane) & 1u;
            const int eqbelow = __popc(em & ltmask);
            const bool seleq = eq && (eqbelow < take);
            if (gt || seleq) {
                int p = pos + __popc(gm & ltmask)
                            + ((eqbelow < take) ? ((gt?0:0), ((seleq||false), 0)) : 0);
                // position among selected: gts below + eq-taken below
                int eqtk = eqbelow < take ? eqbelow : take;
                p = pos + __popc(gm & ltmask) + (eq ? eqtk : ((eqbelow < take) ? eqbelow : take) * 0 + ((__popc(em & ltmask) < take) ? __popc(em & ltmask) : take));
                // simplify: taken eq bits strictly below this lane:
                int eq_taken_below = (eqbelow < take) ? eqbelow : take;
                p = pos + __popc(gm & ltmask) + eq_taken_below;
                if (p < KKEEP) sel[p] = w*256 + step*32 + lane;
            }
            int tk = __popc(em), tkc = (tk < take) ? tk : take;
            pos += __popc(gm) + tkc;
            eqt += tk;
        }
    }
    __syncthreads();

    // weights + Z
    float ez = 0.f;
    if (t < KKEEP) {
        float e = __expf(row[sel[t]] - m);
        wgt[t] = e - e0;
        ez = e;
    }
#pragma unroll
    for (int off = 16; off; off >>= 1)
        ez += __shfl_xor_sync(0xffffffffu, ez, off);
    if (lane == 0) zred[w] = ez;
    __syncthreads();
    if (t == 0) {
        float Z = (float)(SS - KKEEP) * e0;
#pragma unroll
        for (int j = 0; j < 8; j++) Z += zred[j];
        s_invZ = 1.0f / Z;
    }
    __syncthreads();

    // sparse attn @ V: 4-way split over selected rows, 64 d-lanes
    {
        const int c = t >> 6, d = t & 63;
        float acc = 0.f;
        for (int j = c; j < KKEEP; j += 4)
            acc += wgt[j] * Vg[(size_t)sel[j]*DD + d];
        partial[c][d] = acc;
    }
    __syncthreads();
    if (t < 64) {
        float s = partial[0][t] + partial[1][t] + partial[2][t] + partial[3][t]
                + e0 * g_Vsum[bh*DD + t];
        const int b_ = bh >> 4, hh = bh & 15;
        g_AO[((size_t)(b_*SS + q))*HIDD + hh*DD + t] = s * s_invZ;
    }
}

// ---------------- launcher ----------------
extern "C" void kernel_launch(void* const* d_in, const int* in_sizes, int n_in,
                              void* d_out, int out_size)
{
    (void)in_sizes; (void)n_in; (void)out_size;
    const float* x  = (const float*)d_in[0];
    const float* Wq = (const float*)d_in[1];
    const float* bq = (const float*)d_in[2];
    const float* Wk = (const float*)d_in[3];
    const float* bk = (const float*)d_in[4];
    const float* Wv = (const float*)d_in[5];
    const float* bv = (const float*)d_in[6];
    const float* Wo = (const float*)d_in[7];
    const float* bo = (const float*)d_in[8];
    float* out = (float*)d_out;

    const int sc_smem = (128*QP + 64*KP) * 4;   // 68608 B
    cudaFuncSetAttribute(scores_kernel, cudaFuncAttributeMaxDynamicSharedMemorySize,
                         sc_smem);

    dim3 gqkv(HIDD/128, (BB*SS)/128, 3);   // 8 x 32 x 3
    gemm_qkv<<<gqkv, 256>>>(x, Wq, bq, Wk, bk, Wv, bv);

    vsum_kernel<<<BB*HH, 512>>>();

    dim3 gsc(SS/128, SS/128, BB*HH);       // 16 x 16 x 32
    scores_kernel<<<gsc, 256, sc_smem>>>();

    select_kernel<<<BB*HH*SS, 256>>>();

    dim3 go(HIDD/128, (BB*SS)/128);        // 8 x 32
    gemm_o<<<go, 256>>>(Wo, bo, out);
}

// round 14
// speedup vs baseline: 1.6152x; 1.1949x over previous
#include <cuda_runtime.h>
#include <math.h>
#include <stdint.h>

#define BB 2
#define SS 2048
#define HIDD 1024
#define HH 16
#define DD 64
#define KKEEP 204
#define PA 132    // gemm As pad: 132*4 % 16 == 0
#define QP 68     // scores Qs row stride (floats): 272 B, 16B-aligned
#define KP 132    // scores Kt row stride (floats): 528 B, 16B-aligned

// ---------------- packed f32x2 helpers (sm_103a FFMA2 path) ----------------
__device__ __forceinline__ unsigned long long bcast2(float x)
{
    unsigned long long r;
    asm("mov.b64 %0, {%1, %1};" : "=l"(r) : "r"(__float_as_uint(x)));
    return r;
}
__device__ __forceinline__ void unpack2(unsigned long long v, float& x, float& y)
{
    unsigned lo, hi;
    asm("mov.b64 {%0, %1}, %2;" : "=r"(lo), "=r"(hi) : "l"(v));
    x = __uint_as_float(lo); y = __uint_as_float(hi);
}
__device__ __forceinline__ unsigned long long fma2(
    unsigned long long a, unsigned long long b, unsigned long long c)
{
    unsigned long long d;
    asm("fma.rn.f32x2 %0, %1, %2, %3;" : "=l"(d) : "l"(a), "l"(b), "l"(c));
    return d;
}

// ---------------- device scratch ----------------
__device__ float g_Q[BB*HH*SS*DD];     // [b,h,s,d]
__device__ float g_K[BB*HH*SS*DD];
__device__ float g_V[BB*HH*SS*DD];
__device__ float g_S[(size_t)BB*HH*SS*SS];  // scores [bh][q][k]  (536 MB)
__device__ float g_AO[BB*SS*HIDD];     // attention output, [b,s,hid]
__device__ float g_Vsum[BB*HH*DD];     // per-(b,h) column sum of V

// =====================================================================
// GEMM core: 128x128 tile, BK=16, double-buffered, 256 thr, 8x8/thread
// =====================================================================
struct GemmAcc { float a[8][8]; };

__device__ __forceinline__ void gemm_core(
    const float* __restrict__ A, const float* __restrict__ W,
    int bm, int bn, int t,
    float (*As)[16][PA], float (*Bs)[16][128], GemmAcc& R)
{
    unsigned long long acc2[8][4];
#pragma unroll
    for (int i = 0; i < 8; i++)
#pragma unroll
        for (int j = 0; j < 4; j++) acc2[i][j] = 0ULL;

    const int ar0 = t >> 2, ac4 = (t & 3) * 4;
    const int bk0 = t >> 5, bc4 = (t & 31) * 4;

    float4 a0, a1, b0, b1;
    a0 = *(const float4*)&A[(size_t)(bm + ar0     ) * HIDD + ac4];
    a1 = *(const float4*)&A[(size_t)(bm + ar0 + 64) * HIDD + ac4];
    b0 = *(const float4*)&W[(size_t)(bk0    ) * HIDD + bn + bc4];
    b1 = *(const float4*)&W[(size_t)(bk0 + 8) * HIDD + bn + bc4];
    {
        As[0][ac4+0][ar0] = a0.x; As[0][ac4+1][ar0] = a0.y;
        As[0][ac4+2][ar0] = a0.z; As[0][ac4+3][ar0] = a0.w;
        As[0][ac4+0][ar0+64] = a1.x; As[0][ac4+1][ar0+64] = a1.y;
        As[0][ac4+2][ar0+64] = a1.z; As[0][ac4+3][ar0+64] = a1.w;
        *(float4*)&Bs[0][bk0  ][bc4] = b0;
        *(float4*)&Bs[0][bk0+8][bc4] = b1;
    }
    __syncthreads();

    int buf = 0;
    const int tx = t & 15, ty = t >> 4;
    for (int k0 = 16; ; k0 += 16) {
        const bool more = (k0 < HIDD);
        if (more) {
            a0 = *(const float4*)&A[(size_t)(bm + ar0     ) * HIDD + k0 + ac4];
            a1 = *(const float4*)&A[(size_t)(bm + ar0 + 64) * HIDD + k0 + ac4];
            b0 = *(const float4*)&W[(size_t)(k0 + bk0    ) * HIDD + bn + bc4];
            b1 = *(const float4*)&W[(size_t)(k0 + bk0 + 8) * HIDD + bn + bc4];
        }
#pragma unroll
        for (int kk = 0; kk < 16; kk++) {
            float a[8];
            *(float4*)&a[0] = *(float4*)&As[buf][kk][ty*4];
            *(float4*)&a[4] = *(float4*)&As[buf][kk][64 + ty*4];
            ulonglong2 bA = *(const ulonglong2*)&Bs[buf][kk][tx*4];
            ulonglong2 bB = *(const ulonglong2*)&Bs[buf][kk][64 + tx*4];
#pragma unroll
            for (int i = 0; i < 8; i++) {
                unsigned long long pa = bcast2(a[i]);
                acc2[i][0] = fma2(pa, bA.x, acc2[i][0]);
                acc2[i][1] = fma2(pa, bA.y, acc2[i][1]);
                acc2[i][2] = fma2(pa, bB.x, acc2[i][2]);
                acc2[i][3] = fma2(pa, bB.y, acc2[i][3]);
            }
        }
        if (!more) break;
        const int nb = buf ^ 1;
        As[nb][ac4+0][ar0] = a0.x; As[nb][ac4+1][ar0] = a0.y;
        As[nb][ac4+2][ar0] = a0.z; As[nb][ac4+3][ar0] = a0.w;
        As[nb][ac4+0][ar0+64] = a1.x; As[nb][ac4+1][ar0+64] = a1.y;
        As[nb][ac4+2][ar0+64] = a1.z; As[nb][ac4+3][ar0+64] = a1.w;
        *(float4*)&Bs[nb][bk0  ][bc4] = b0;
        *(float4*)&Bs[nb][bk0+8][bc4] = b1;
        __syncthreads();
        buf = nb;
    }

#pragma unroll
    for (int i = 0; i < 8; i++)
#pragma unroll
        for (int jp = 0; jp < 4; jp++)
            unpack2(acc2[i][jp], R.a[i][2*jp], R.a[i][2*jp+1]);
}

__device__ __forceinline__ int row_of(int i, int tyx) {
    return (i < 4) ? (tyx*4 + i) : (64 + tyx*4 + i - 4);
}

__global__ __launch_bounds__(256, 2)
void gemm_qkv(const float* __restrict__ x,
              const float* __restrict__ Wq, const float* __restrict__ bq,
              const float* __restrict__ Wk, const float* __restrict__ bk,
              const float* __restrict__ Wv, const float* __restrict__ bv)
{
    __shared__ __align__(16) float As[2][16][PA];
    __shared__ __align__(16) float Bs[2][16][128];
    const int z = blockIdx.z;
    const float* W    = (z == 0) ? Wq : (z == 1) ? Wk : Wv;
    const float* bias = (z == 0) ? bq : (z == 1) ? bk : bv;
    float* C          = (z == 0) ? g_Q : (z == 1) ? g_K : g_V;

    const int bm = blockIdx.y * 128, bn = blockIdx.x * 128;
    const int t = threadIdx.x, tx = t & 15, ty = t >> 4;
    GemmAcc R;
    gemm_core(x, W, bm, bn, t, As, Bs, R);

#pragma unroll
    for (int i = 0; i < 8; i++) {
        const int m = bm + row_of(i, ty);
        const int b_ = m >> 11, s = m & 2047;
#pragma unroll
        for (int j = 0; j < 8; j++) {
            const int n = bn + row_of(j, tx);
            const int h = n >> 6, d = n & 63;
            C[(((size_t)(b_*HH + h))*SS + s)*DD + d] = R.a[i][j] + bias[n];
        }
    }
}

__global__ __launch_bounds__(256, 2)
void gemm_o(const float* __restrict__ Wo, const float* __restrict__ bo,
            float* __restrict__ out)
{
    __shared__ __align__(16) float As[2][16][PA];
    __shared__ __align__(16) float Bs[2][16][128];
    const int bm = blockIdx.y * 128, bn = blockIdx.x * 128;
    const int t = threadIdx.x, tx = t & 15, ty = t >> 4;
    GemmAcc R;
    gemm_core(g_AO, Wo, bm, bn, t, As, Bs, R);

#pragma unroll
    for (int i = 0; i < 8; i++) {
        const int m = bm + row_of(i, ty);
#pragma unroll
        for (int j = 0; j < 8; j++) {
            const int n = bn + row_of(j, tx);
            out[(size_t)m * HIDD + n] = R.a[i][j] + bo[n];
        }
    }
}

// ---------------- per-(b,h) V column sums ----------------
__global__ __launch_bounds__(512)
void vsum_kernel()
{
    __shared__ float red[8][64];
    const int bh = blockIdx.x;
    const int d = threadIdx.x & 63, sub = threadIdx.x >> 6;
    const float* vp = g_V + (size_t)bh*SS*DD + (size_t)sub*256*DD + d;
    float s0=0,s1=0,s2=0,s3=0;
#pragma unroll 4
    for (int i = 0; i < 256; i += 4) {
        s0 += vp[(size_t)(i+0)*DD];
        s1 += vp[(size_t)(i+1)*DD];
        s2 += vp[(size_t)(i+2)*DD];
        s3 += vp[(size_t)(i+3)*DD];
    }
    red[sub][d] = (s0+s1)+(s2+s3);
    __syncthreads();
    if (sub == 0) {
        float a = 0.f;
#pragma unroll
        for (int j = 0; j < 8; j++) a += red[j][d];
        g_Vsum[bh*DD + d] = a;
    }
}

// =====================================================================
// scores kernel: S[bh][q][k] = (Q . K) / 8, 128x128 tiles, K=64
// =====================================================================
__global__ __launch_bounds__(256, 2)
void scores_kernel()
{
    extern __shared__ __align__(16) float sm[];
    float* Qs = sm;               // [128][QP]
    float* Kt = sm + 128*QP;      // [64][KP]  (d-major, transposed)

    const int bh = blockIdx.z;
    const int bm = blockIdx.y * 128;
    const int bn = blockIdx.x * 128;
    const int t  = threadIdx.x;
    const int tx = t & 15, ty = t >> 4;
    const float* Qg = g_Q + (size_t)bh*SS*DD;
    const float* Kg = g_K + (size_t)bh*SS*DD;

#pragma unroll
    for (int it = 0; it < 8; it++) {
        int idx = it*256 + t;
        int r = idx >> 4, c4 = (idx & 15)*4;
        *(float4*)&Qs[r*QP + c4] = *(const float4*)&Qg[(size_t)(bm + r)*DD + c4];
    }
#pragma unroll
    for (int it = 0; it < 8; it++) {
        int idx = it*256 + t;
        int key = idx >> 4, c4 = idx & 15;
        float4 v = *(const float4*)&Kg[(size_t)(bn + key)*DD + c4*4];
        Kt[(c4*4+0)*KP + key] = v.x;
        Kt[(c4*4+1)*KP + key] = v.y;
        Kt[(c4*4+2)*KP + key] = v.z;
        Kt[(c4*4+3)*KP + key] = v.w;
    }
    __syncthreads();

    unsigned long long acc2[8][4];
#pragma unroll
    for (int i = 0; i < 8; i++)
#pragma unroll
        for (int j = 0; j < 4; j++) acc2[i][j] = 0ULL;

#pragma unroll
    for (int d4 = 0; d4 < DD; d4 += 4) {
        float4 qv[8];
#pragma unroll
        for (int i = 0; i < 8; i++)
            qv[i] = *(const float4*)&Qs[(ty*8 + i)*QP + d4];
#pragma unroll
        for (int dd = 0; dd < 4; dd++) {
            ulonglong2 ka = *(const ulonglong2*)&Kt[(d4+dd)*KP + tx*4];
            ulonglong2 kb = *(const ulonglong2*)&Kt[(d4+dd)*KP + 64 + tx*4];
#pragma unroll
            for (int i = 0; i < 8; i++) {
                float qd = (dd==0)?qv[i].x:(dd==1)?qv[i].y:(dd==2)?qv[i].z:qv[i].w;
                unsigned long long pq = bcast2(qd);
                acc2[i][0] = fma2(pq, ka.x, acc2[i][0]);
                acc2[i][1] = fma2(pq, ka.y, acc2[i][1]);
                acc2[i][2] = fma2(pq, kb.x, acc2[i][2]);
                acc2[i][3] = fma2(pq, kb.y, acc2[i][3]);
            }
        }
    }

    const float scale = 0.125f;
    float* Sg = g_S + (size_t)bh*SS*SS;
#pragma unroll
    for (int i = 0; i < 8; i++) {
        float v[8];
#pragma unroll
        for (int jp = 0; jp < 4; jp++) unpack2(acc2[i][jp], v[2*jp], v[2*jp+1]);
        const size_t roff = (size_t)(bm + ty*8 + i)*SS + bn;
        *(float4*)&Sg[roff + tx*4] =
            make_float4(v[0]*scale, v[1]*scale, v[2]*scale, v[3]*scale);
        *(float4*)&Sg[roff + 64 + tx*4] =
            make_float4(v[4]*scale, v[5]*scale, v[6]*scale, v[7]*scale);
    }
}

// =====================================================================
// select kernel: one block per query row. exact top-204 + sparse softmax@V
// key cache in smem + parallel suffix-scan bin find (no serial t0 scan)
// =====================================================================
__device__ __forceinline__ unsigned fkey(float f)
{
    unsigned u = __float_as_uint(f);
    return (u & 0x80000000u) ? ~u : (u | 0x80000000u);
}
__device__ __forceinline__ float fkeyinv(unsigned k)
{
    unsigned u = (k & 0x80000000u) ? (k & 0x7fffffffu) : ~k;
    return __uint_as_float(u);
}

__global__ __launch_bounds__(256, 8)
void select_kernel()
{
    __shared__ __align__(16) float row[SS];
    __shared__ __align__(16) unsigned ukey[SS];
    __shared__ int   hist[256];
    __shared__ int   wtot[8];
    __shared__ int   wgt_cnt[8], weq_cnt[8], weq_b[8], wbase[8];
    __shared__ unsigned wmax[8];
    __shared__ unsigned gmask[8][8], emask[8][8];
    __shared__ int   sel[KKEEP];
    __shared__ float wgt[KKEEP];
    __shared__ float partial[4][64];
    __shared__ float zred[8];
    __shared__ int   sbin, srem;
    __shared__ float s_invZ;

    const int t = threadIdx.x, w = t >> 5, lane = t & 31;
    const unsigned ltmask = (1u << lane) - 1u;
    const int rowid = blockIdx.x;            // = bh*2048 + q
    const int bh = rowid >> 11, q = rowid & 2047;
    const float* Sg = g_S + (size_t)rowid * SS;
    const float* Vg = g_V + (size_t)bh*SS*DD;

    // load row + zero hist
    {
        const float4* s4 = (const float4*)Sg;
#pragma unroll
        for (int it = 0; it < 2; it++)
            ((float4*)row)[it*256 + t] = s4[it*256 + t];
    }
    hist[t] = 0;
    __syncthreads();

    // key generation + pass-0 histogram (match-aggregated) + row max
    unsigned mymax = 0;
#pragma unroll
    for (int step = 0; step < 8; step++) {
        const int i = w*256 + step*32 + lane;
        unsigned u = fkey(row[i]);
        ukey[i] = u;
        if (u > mymax) mymax = u;
        unsigned bin = u >> 24;
        unsigned mk = __match_any_sync(0xffffffffu, bin);
        if (lane == (__ffs(mk) - 1))
            atomicAdd(&hist[bin], __popc(mk));
    }
#pragma unroll
    for (int off = 16; off; off >>= 1) {
        unsigned o = __shfl_xor_sync(0xffffffffu, mymax, off);
        if (o > mymax) mymax = o;
    }
    if (lane == 0) wmax[w] = mymax;
    __syncthreads();
    unsigned gmax = wmax[0];
#pragma unroll
    for (int j = 1; j < 8; j++) if (wmax[j] > gmax) gmax = wmax[j];
    const float m  = fmaxf(fkeyinv(gmax), 0.0f);   // sparse row contains zeros
    const float e0 = __expf(-m);

    // radix select with parallel suffix-scan bin find
    int rem = KKEEP;
    unsigned prefix = 0;
#pragma unroll
    for (int pass = 0; pass < 4; pass++) {
        const int shift = 24 - pass*8;
        if (pass > 0) {
            hist[t] = 0;
            __syncthreads();
#pragma unroll
            for (int step = 0; step < 8; step++) {
                unsigned u = ukey[step*256 + t];
                if ((u >> (shift + 8)) == prefix)
                    atomicAdd(&hist[(u >> shift) & 255], 1);
            }
        }
        __syncthreads();
        // suffix sum over bins (bin index = t): S(t) = sum_{b>=t} hist[b]
        const int hv = hist[t];
        int v = hv;
#pragma unroll
        for (int off = 1; off < 32; off <<= 1) {
            int o = __shfl_down_sync(0xffffffffu, v, off);
            if (lane + off < 32) v += o;
        }
        if (lane == 0) wtot[w] = v;    // total of this warp's 32 bins
        // restore per-lane inclusive suffix within warp
        // (v currently holds suffix only at... recompute properly below)
        __syncthreads();
        // v at each lane: inclusive suffix within warp (computed above per-lane)
        int offs = 0;
#pragma unroll
        for (int ww = 0; ww < 8; ww++)
            if (ww > w) offs += wtot[ww];
        const int S = v + offs;
        if (S >= rem && S - hv < rem) {
            sbin = t;
            srem = rem - (S - hv);
        }
        __syncthreads();
        prefix = (prefix << 8) | (unsigned)sbin;
        rem = srem;
        __syncthreads();
    }
    const unsigned T = prefix;
    const int need_eq = rem;

    // count gt/eq per warp over its contiguous 256-elem segment; cache masks
    int cgt = 0, ceq = 0;
#pragma unroll
    for (int step = 0; step < 8; step++) {
        unsigned u = ukey[w*256 + step*32 + lane];
        unsigned gm = __ballot_sync(0xffffffffu, u > T);
        unsigned em = __ballot_sync(0xffffffffu, u == T);
        cgt += __popc(gm);
        ceq += __popc(em);
        if (lane == 0) { gmask[w][step] = gm; emask[w][step] = em; }
    }
    if (lane == 0) { wgt_cnt[w] = cgt; weq_cnt[w] = ceq; }
    __syncthreads();
    if (t == 0) {
        int run = 0, eqr = 0;
        for (int ww = 0; ww < 8; ww++) {
            weq_b[ww] = eqr;
            int take = need_eq - eqr;
            if (take < 0) take = 0;
            if (take > weq_cnt[ww]) take = weq_cnt[ww];
            wbase[ww] = run;
            run += wgt_cnt[ww] + take;
            eqr += weq_cnt[ww];
        }
    }
    __syncthreads();

    // write selection list from cached masks
    {
        int pos = wbase[w], eqt = weq_b[w];
#pragma unroll
        for (int step = 0; step < 8; step++) {
            const unsigned gm = gmask[w][step];
            const unsigned em = emask[w][step];
            int take = need_eq - eqt;
            if (take < 0) take = 0;
            const bool gt = (gm >> lane) & 1u;
            const bool eq = (em >> lane) & 1u;
            const int eqbelow = __popc(em & ltmask);
            const bool seleq = eq && (eqbelow < take);
            if (gt || seleq) {
                const int eq_taken_below = (eqbelow < take) ? eqbelow : take;
                const int p = pos + __popc(gm & ltmask) + eq_taken_below;
                if (p < KKEEP) sel[p] = w*256 + step*32 + lane;
            }
            const int tk = __popc(em);
            pos += __popc(gm) + ((tk < take) ? tk : take);
            eqt += tk;
        }
    }
    __syncthreads();

    // weights + Z
    float ez = 0.f;
    if (t < KKEEP) {
        float e = __expf(row[sel[t]] - m);
        wgt[t] = e - e0;
        ez = e;
    }
#pragma unroll
    for (int off = 16; off; off >>= 1)
        ez += __shfl_xor_sync(0xffffffffu, ez, off);
    if (lane == 0) zred[w] = ez;
    __syncthreads();
    if (t == 0) {
        float Z = (float)(SS - KKEEP) * e0;
#pragma unroll
        for (int j = 0; j < 8; j++) Z += zred[j];
        s_invZ = 1.0f / Z;
    }
    __syncthreads();

    // sparse attn @ V
    {
        const int c = t >> 6, d = t & 63;
        float acc = 0.f;
        for (int j = c; j < KKEEP; j += 4)
            acc += wgt[j] * Vg[(size_t)sel[j]*DD + d];
        partial[c][d] = acc;
    }
    __syncthreads();
    if (t < 64) {
        float s = partial[0][t] + partial[1][t] + partial[2][t] + partial[3][t]
                + e0 * g_Vsum[bh*DD + t];
        const int b_ = bh >> 4, hh = bh & 15;
        g_AO[((size_t)(b_*SS + q))*HIDD + hh*DD + t] = s * s_invZ;
    }
}

// ---------------- launcher ----------------
extern "C" void kernel_launch(void* const* d_in, const int* in_sizes, int n_in,
                              void* d_out, int out_size)
{
    (void)in_sizes; (void)n_in; (void)out_size;
    const float* x  = (const float*)d_in[0];
    const float* Wq = (const float*)d_in[1];
    const float* bq = (const float*)d_in[2];
    const float* Wk = (const float*)d_in[3];
    const float* bk = (const float*)d_in[4];
    const float* Wv = (const float*)d_in[5];
    const float* bv = (const float*)d_in[6];
    const float* Wo = (const float*)d_in[7];
    const float* bo = (const float*)d_in[8];
    float* out = (float*)d_out;

    const int sc_smem = (128*QP + 64*KP) * 4;   // 68608 B
    cudaFuncSetAttribute(scores_kernel, cudaFuncAttributeMaxDynamicSharedMemorySize,
                         sc_smem);

    dim3 gqkv(HIDD/128, (BB*SS)/128, 3);   // 8 x 32 x 3
    gemm_qkv<<<gqkv, 256>>>(x, Wq, bq, Wk, bk, Wv, bv);

    vsum_kernel<<<BB*HH, 512>>>();

    dim3 gsc(SS/128, SS/128, BB*HH);       // 16 x 16 x 32
    scores_kernel<<<gsc, 256, sc_smem>>>();

    select_kernel<<<BB*HH*SS, 256>>>();

    dim3 go(HIDD/128, (BB*SS)/128);        // 8 x 32
    gemm_o<<<go, 256>>>(Wo, bo, out);
}